// round 2
// baseline (speedup 1.0000x reference)
#include <cuda_runtime.h>
#include <math.h>

typedef unsigned long long ull;

#define BB 256
#define NN 128
#define LL 2048
#define DD 64
#define PADW 11

// ---- f32x2 helpers (Blackwell packed fp32) ----
__device__ __forceinline__ ull pk2(float lo, float hi) {
    ull r; asm("mov.b64 %0, {%1,%2};" : "=l"(r) : "f"(lo), "f"(hi)); return r;
}
__device__ __forceinline__ void upk2(ull p, float& lo, float& hi) {
    asm("mov.b64 {%0,%1}, %2;" : "=f"(lo), "=f"(hi) : "l"(p));
}
#define FMA2(acc, a, b) asm("fma.rn.f32x2 %0, %1, %2, %0;" : "+l"(acc) : "l"(a), "l"(b))

// ---- scratch (no cudaMalloc allowed) ----
__device__ float g_bufA[(size_t)BB * LL * DD];
__device__ float g_bufB[(size_t)BB * LL * DD];
__device__ float g_comp[BB * DD];
__device__ float g_prot[BB * DD];

// ===========================================================================
// GNN: embed atoms + 3 layers + masked mean -> g_comp.  1 block / batch.
// dyn smem: xs[128*68] hs[128*68] Wt[64*68] bv[64]  = 87296 B
// ===========================================================================
__global__ void __launch_bounds__(256) gnn_kernel(
    const int* __restrict__ atoms, const float* __restrict__ atoms_mask,
    const float* __restrict__ adj, const float* __restrict__ emb_fp,
    const float* __restrict__ W_gnn, const float* __restrict__ b_gnn)
{
    extern __shared__ float sm[];
    float* xs = sm;
    float* hs = xs + 128 * 68;
    float* Wt = hs + 128 * 68;
    float* bv = Wt + 64 * 68;

    const int b = blockIdx.x, tid = threadIdx.x;

    for (int o = tid; o < NN * DD; o += 256) {
        int n = o >> 6, d = o & 63;
        xs[n * 68 + d] = emb_fp[atoms[b * NN + n] * DD + d];
    }

    for (int layer = 0; layer < 3; layer++) {
        __syncthreads();
        for (int o = tid; o < DD * DD; o += 256) {
            int e = o >> 6, d = o & 63;
            Wt[d * 68 + e] = W_gnn[layer * DD * DD + o];
        }
        if (tid < DD) bv[tid] = b_gnn[layer * DD + tid];
        __syncthreads();

        // hs = relu(xs @ W^T + b)
        for (int g = tid; g < NN * 16; g += 256) {
            int n = g >> 4, e4 = (g & 15) * 4;
            float a0 = bv[e4], a1 = bv[e4+1], a2 = bv[e4+2], a3 = bv[e4+3];
            const float* xr = xs + n * 68;
            #pragma unroll 4
            for (int d = 0; d < DD; d++) {
                float x = xr[d];
                float4 w = *(const float4*)(Wt + d * 68 + e4);
                a0 = fmaf(x, w.x, a0); a1 = fmaf(x, w.y, a1);
                a2 = fmaf(x, w.z, a2); a3 = fmaf(x, w.w, a3);
            }
            float* hr = hs + n * 68 + e4;
            hr[0] = fmaxf(a0, 0.f); hr[1] = fmaxf(a1, 0.f);
            hr[2] = fmaxf(a2, 0.f); hr[3] = fmaxf(a3, 0.f);
        }
        __syncthreads();

        // xs += adj @ hs
        const float* adjb = adj + (size_t)b * NN * NN;
        for (int g = tid; g < NN * 16; g += 256) {
            int n = g >> 4, d4 = (g & 15) * 4;
            float* xp = xs + n * 68 + d4;
            float a0 = xp[0], a1 = xp[1], a2 = xp[2], a3 = xp[3];
            const float* ar = adjb + n * NN;
            #pragma unroll 4
            for (int m = 0; m < NN; m++) {
                float av = __ldg(ar + m);
                float4 h = *(const float4*)(hs + m * 68 + d4);
                a0 = fmaf(av, h.x, a0); a1 = fmaf(av, h.y, a1);
                a2 = fmaf(av, h.z, a2); a3 = fmaf(av, h.w, a3);
            }
            xp[0] = a0; xp[1] = a1; xp[2] = a2; xp[3] = a3;
        }
    }
    __syncthreads();

    if (tid < DD) {
        float s = 0.f, ms = 0.f;
        for (int n = 0; n < NN; n++) {
            float m = atoms_mask[b * NN + n];
            s += xs[n * 68 + tid] * m;
            ms += m;
        }
        g_comp[b * DD + tid] = s / (ms + 1e-6f);
    }
}

// ===========================================================================
// Embed protein: g_bufA = emb_word[amino]
// ===========================================================================
__global__ void __launch_bounds__(256) embed_kernel(
    const int* __restrict__ amino, const float* __restrict__ emb)
{
    int idx = blockIdx.x * 256 + threadIdx.x;   // over B*L*16 float4s
    if (idx >= BB * LL * 16) return;
    int q = idx & 15, row = idx >> 4;
    ((float4*)g_bufA)[idx] = ((const float4*)emb)[amino[row] * 16 + q];
}

// ===========================================================================
// Conv 23x23 same + bias + relu, fp32 via packed f32x2.
// Tile 64 rows x 64 cols, 128 thr: thread = 8 rows x 4 cols.
// srcSel: 0 = A->B, 1 = B->A
// ===========================================================================
__global__ void __launch_bounds__(128, 3) conv_kernel(
    const float* __restrict__ ck, const float* __restrict__ cb,
    int layer, int srcSel)
{
    __shared__ float sh[86][88];
    __shared__ ull ksh[37][12];   // kernel row pairs, zero-padded index i+7

    const float* in = srcSel ? g_bufB : g_bufA;
    float* out      = srcSel ? g_bufA : g_bufB;

    const int b = blockIdx.y, h0 = blockIdx.x * 64, tid = threadIdx.x;

    const float* kk = ck + layer * 529;
    for (int idx = tid; idx < 37 * 12; idx += 128) {
        int i7 = idx / 12, jj = idx % 12, i = i7 - 7;
        float lo = 0.f, hi = 0.f;
        if (i >= 0 && i <= 22) {
            lo = kk[i * 23 + 2 * jj];
            if (2 * jj + 1 < 23) hi = kk[i * 23 + 2 * jj + 1];
        }
        ksh[i7][jj] = pk2(lo, hi);
    }
    for (int idx = tid; idx < 86 * 88; idx += 128) ((float*)sh)[idx] = 0.f;
    __syncthreads();

    const float* inb = in + (size_t)b * LL * DD;
    for (int idx = tid; idx < 86 * 16; idx += 128) {
        int s = idx >> 4, q = idx & 15;
        int gh = h0 + s - PADW;
        if (gh >= 0 && gh < LL) {
            float4 v = ((const float4*)(inb + (size_t)gh * DD))[q];
            float* p = &sh[s][PADW + 4 * q];
            p[0] = v.x; p[1] = v.y; p[2] = v.z; p[3] = v.w;
        }
    }
    __syncthreads();

    const int tx = tid & 15, ty = tid >> 4;
    const int w0 = tx * 4;

    ull acc[8][4];
    #pragma unroll
    for (int r = 0; r < 8; r++) acc[r][0] = acc[r][1] = acc[r][2] = acc[r][3] = 0ull;

    const float* base = &sh[ty * 8][w0];

    #pragma unroll 1
    for (int ir = 0; ir < 30; ir++) {
        ull pe[13], po[13];
        const float4* rp = (const float4*)(base + ir * 88);
        float4 v = rp[0];
        pe[0] = pk2(v.x, v.y); pe[1] = pk2(v.z, v.w); po[0] = pk2(v.y, v.z);
        float carry = v.w;
        #pragma unroll
        for (int q = 1; q <= 5; q++) {
            float4 u = rp[q];
            po[2*q-1] = pk2(carry, u.x);
            pe[2*q]   = pk2(u.x, u.y);
            pe[2*q+1] = pk2(u.z, u.w);
            po[2*q]   = pk2(u.y, u.z);
            carry = u.w;
        }
        { float4 u = rp[6];
          po[11] = pk2(carry, u.x);
          pe[12] = pk2(u.x, u.y);
          po[12] = pk2(u.y, u.z); }

        #pragma unroll
        for (int r = 0; r < 8; r++) {
            const ull* kp = ksh[ir - r + 7];   // zero rows when out of range
            #pragma unroll
            for (int jj = 0; jj < 12; jj++) {
                ull kv = kp[jj];
                FMA2(acc[r][0], pe[jj],   kv);
                FMA2(acc[r][1], po[jj],   kv);
                FMA2(acc[r][2], pe[jj+1], kv);
                FMA2(acc[r][3], po[jj+1], kv);
            }
        }
    }

    const float bias = cb[layer];
    float* outb = out + (size_t)b * LL * DD + (size_t)(h0 + ty * 8) * DD + w0;
    #pragma unroll
    for (int r = 0; r < 8; r++) {
        float4 v; float lo, hi;
        upk2(acc[r][0], lo, hi); v.x = fmaxf(lo + hi + bias, 0.f);
        upk2(acc[r][1], lo, hi); v.y = fmaxf(lo + hi + bias, 0.f);
        upk2(acc[r][2], lo, hi); v.z = fmaxf(lo + hi + bias, 0.f);
        upk2(acc[r][3], lo, hi); v.w = fmaxf(lo + hi + bias, 0.f);
        *(float4*)(outb + (size_t)r * DD) = v;
    }
}

// ===========================================================================
// Attention + protein pooling. 1 block / batch, 256 threads.
// dyn smem: Wt[64*68] + hsv[256*65] = 83968 B
// ===========================================================================
__global__ void __launch_bounds__(256) att_kernel(
    const float* __restrict__ amino_mask,
    const float* __restrict__ W_att, const float* __restrict__ b_att)
{
    extern __shared__ float sm[];
    float* Wt  = sm;                  // 64*68
    float* hsa = sm + 64 * 68;        // 256*65 per-thread hs scratch
    __shared__ float hv[64], sprot[64], sb[64], ssum;

    const int b = blockIdx.x, tid = threadIdx.x;
    const float* ps = g_bufB + (size_t)b * LL * DD;

    for (int o = tid; o < DD * DD; o += 256) {
        int e = o >> 6, d = o & 63;
        Wt[d * 68 + e] = W_att[o];
    }
    if (tid < 64) { sprot[tid] = 0.f; sb[tid] = b_att[tid]; }
    if (tid == 0) ssum = 0.f;
    __syncthreads();

    if (tid < 64) {
        float a = sb[tid];
        const float* wr = W_att + tid * 64;
        for (int d = 0; d < DD; d++) a = fmaf(g_comp[b * DD + d], wr[d], a);
        hv[tid] = fmaxf(a, 0.f);
    }
    __syncthreads();

    float prl[64];
    #pragma unroll
    for (int d = 0; d < 64; d++) prl[d] = 0.f;
    float msum = 0.f;
    float* myhs = hsa + tid * 65;

    for (int l = tid; l < LL; l += 256) {
        float m = amino_mask[b * LL + l];
        msum += m;
        const float4* xr = (const float4*)(ps + (size_t)l * DD);
        float4 x4[16];
        #pragma unroll
        for (int q = 0; q < 16; q++) x4[q] = xr[q];
        float wh = 0.f;
        #pragma unroll
        for (int e4 = 0; e4 < 64; e4 += 4) {
            float a0 = sb[e4], a1 = sb[e4+1], a2 = sb[e4+2], a3 = sb[e4+3];
            #pragma unroll
            for (int d = 0; d < DD; d++) {
                float x = ((const float*)x4)[d];
                float4 w = *(const float4*)(Wt + d * 68 + e4);
                a0 = fmaf(x, w.x, a0); a1 = fmaf(x, w.y, a1);
                a2 = fmaf(x, w.z, a2); a3 = fmaf(x, w.w, a3);
            }
            a0 = fmaxf(a0, 0.f) * m; a1 = fmaxf(a1, 0.f) * m;
            a2 = fmaxf(a2, 0.f) * m; a3 = fmaxf(a3, 0.f) * m;
            myhs[e4] = a0; myhs[e4+1] = a1; myhs[e4+2] = a2; myhs[e4+3] = a3;
            wh = fmaf(hv[e4], a0, wh);   wh = fmaf(hv[e4+1], a1, wh);
            wh = fmaf(hv[e4+2], a2, wh); wh = fmaf(hv[e4+3], a3, wh);
        }
        float w = tanhf(wh);
        #pragma unroll
        for (int d = 0; d < 64; d++) prl[d] = fmaf(w, myhs[d], prl[d]);
    }

    for (int off = 16; off; off >>= 1) msum += __shfl_xor_sync(~0u, msum, off);
    if ((tid & 31) == 0) atomicAdd(&ssum, msum);
    #pragma unroll
    for (int d = 0; d < 64; d++) {
        float v = prl[d];
        for (int off = 16; off; off >>= 1) v += __shfl_xor_sync(~0u, v, off);
        if ((tid & 31) == 0) atomicAdd(&sprot[d], v);
    }
    __syncthreads();
    if (tid < 64) g_prot[b * DD + tid] = sprot[tid] / (ssum + 1e-6f);
}

// ===========================================================================
// Output MLP: cat=[comp,prot]; 2x relu(cat@W^T+b); out = cat@W_int^T + b_int
// ===========================================================================
__global__ void __launch_bounds__(128) out_kernel(
    const float* __restrict__ W_out, const float* __restrict__ b_out,
    const float* __restrict__ W_int, const float* __restrict__ b_int,
    float* __restrict__ out)
{
    __shared__ float cat[128], nxt[128];
    const int b = blockIdx.x, t = threadIdx.x;
    if (t < 64) { cat[t] = g_comp[b * 64 + t]; cat[64 + t] = g_prot[b * 64 + t]; }
    __syncthreads();
    for (int j = 0; j < 2; j++) {
        float a = b_out[j * 128 + t];
        const float* wr = W_out + j * 16384 + t * 128;
        #pragma unroll 4
        for (int d = 0; d < 128; d++) a = fmaf(cat[d], wr[d], a);
        nxt[t] = fmaxf(a, 0.f);
        __syncthreads();
        cat[t] = nxt[t];
        __syncthreads();
    }
    if (t < 2) {
        float a = b_int[t];
        const float* wr = W_int + t * 128;
        for (int d = 0; d < 128; d++) a = fmaf(cat[d], wr[d], a);
        out[b * 2 + t] = a;
    }
}

// ===========================================================================
extern "C" void kernel_launch(void* const* d_in, const int* in_sizes, int n_in,
                              void* d_out, int out_size)
{
    const int*   atoms      = (const int*)  d_in[0];
    const float* atoms_mask = (const float*)d_in[1];
    const float* adjacency  = (const float*)d_in[2];
    const int*   amino      = (const int*)  d_in[3];
    const float* amino_mask = (const float*)d_in[4];
    const float* emb_fp     = (const float*)d_in[5];
    const float* emb_word   = (const float*)d_in[6];
    const float* W_gnn      = (const float*)d_in[7];
    const float* b_gnn      = (const float*)d_in[8];
    const float* conv_k     = (const float*)d_in[9];
    const float* conv_b     = (const float*)d_in[10];
    const float* W_att      = (const float*)d_in[11];
    const float* b_att      = (const float*)d_in[12];
    const float* W_out      = (const float*)d_in[13];
    const float* b_out      = (const float*)d_in[14];
    const float* W_int      = (const float*)d_in[15];
    const float* b_int      = (const float*)d_in[16];
    float* out = (float*)d_out;

    cudaFuncSetAttribute(gnn_kernel, cudaFuncAttributeMaxDynamicSharedMemorySize, 87296);
    cudaFuncSetAttribute(att_kernel, cudaFuncAttributeMaxDynamicSharedMemorySize, 83968);

    gnn_kernel<<<BB, 256, 87296>>>(atoms, atoms_mask, adjacency, emb_fp, W_gnn, b_gnn);

    embed_kernel<<<(BB * LL * 16 + 255) / 256, 256>>>(amino, emb_word);

    dim3 cgrid(LL / 64, BB);
    conv_kernel<<<cgrid, 128>>>(conv_k, conv_b, 0, 0);   // A -> B
    conv_kernel<<<cgrid, 128>>>(conv_k, conv_b, 1, 1);   // B -> A
    conv_kernel<<<cgrid, 128>>>(conv_k, conv_b, 2, 0);   // A -> B

    att_kernel<<<BB, 256, 83968>>>(amino_mask, W_att, b_att);

    out_kernel<<<BB, 128>>>(W_out, b_out, W_int, b_int, out);
}

// round 3
// speedup vs baseline: 1.0006x; 1.0006x over previous
#include <cuda_runtime.h>
#include <math.h>

typedef unsigned long long ull;

#define BB 256
#define NN 128
#define LL 2048
#define DD 64
#define PADW 11

// ---- f32x2 helpers (Blackwell packed fp32) ----
__device__ __forceinline__ ull pk2(float lo, float hi) {
    ull r; asm("mov.b64 %0, {%1,%2};" : "=l"(r) : "f"(lo), "f"(hi)); return r;
}
__device__ __forceinline__ void upk2(ull p, float& lo, float& hi) {
    asm("mov.b64 {%0,%1}, %2;" : "=f"(lo), "=f"(hi) : "l"(p));
}
#define FMA2(acc, a, b) asm("fma.rn.f32x2 %0, %1, %2, %0;" : "+l"(acc) : "l"(a), "l"(b))

// ---- scratch (no cudaMalloc allowed) ----
__device__ float g_bufA[(size_t)BB * LL * DD];
__device__ float g_bufB[(size_t)BB * LL * DD];
__device__ float g_comp[BB * DD];
__device__ float g_prot[BB * DD];

// ===========================================================================
// GNN: embed atoms + 3 layers + masked mean -> g_comp.  1 block / batch.
// dyn smem: xs[128*68] hs[128*68] Wt[64*68] bv[64]  = 87296 B
// ===========================================================================
__global__ void __launch_bounds__(256) gnn_kernel(
    const int* __restrict__ atoms, const float* __restrict__ atoms_mask,
    const float* __restrict__ adj, const float* __restrict__ emb_fp,
    const float* __restrict__ W_gnn, const float* __restrict__ b_gnn)
{
    extern __shared__ float sm[];
    float* xs = sm;
    float* hs = xs + 128 * 68;
    float* Wt = hs + 128 * 68;
    float* bv = Wt + 64 * 68;

    const int b = blockIdx.x, tid = threadIdx.x;

    for (int o = tid; o < NN * DD; o += 256) {
        int n = o >> 6, d = o & 63;
        xs[n * 68 + d] = emb_fp[atoms[b * NN + n] * DD + d];
    }

    for (int layer = 0; layer < 3; layer++) {
        __syncthreads();
        for (int o = tid; o < DD * DD; o += 256) {
            int e = o >> 6, d = o & 63;
            Wt[d * 68 + e] = W_gnn[layer * DD * DD + o];
        }
        if (tid < DD) bv[tid] = b_gnn[layer * DD + tid];
        __syncthreads();

        // hs = relu(xs @ W^T + b)
        for (int g = tid; g < NN * 16; g += 256) {
            int n = g >> 4, e4 = (g & 15) * 4;
            float a0 = bv[e4], a1 = bv[e4+1], a2 = bv[e4+2], a3 = bv[e4+3];
            const float* xr = xs + n * 68;
            #pragma unroll 4
            for (int d = 0; d < DD; d++) {
                float x = xr[d];
                float4 w = *(const float4*)(Wt + d * 68 + e4);
                a0 = fmaf(x, w.x, a0); a1 = fmaf(x, w.y, a1);
                a2 = fmaf(x, w.z, a2); a3 = fmaf(x, w.w, a3);
            }
            float* hr = hs + n * 68 + e4;
            hr[0] = fmaxf(a0, 0.f); hr[1] = fmaxf(a1, 0.f);
            hr[2] = fmaxf(a2, 0.f); hr[3] = fmaxf(a3, 0.f);
        }
        __syncthreads();

        // xs += adj @ hs
        const float* adjb = adj + (size_t)b * NN * NN;
        for (int g = tid; g < NN * 16; g += 256) {
            int n = g >> 4, d4 = (g & 15) * 4;
            float* xp = xs + n * 68 + d4;
            float a0 = xp[0], a1 = xp[1], a2 = xp[2], a3 = xp[3];
            const float* ar = adjb + n * NN;
            #pragma unroll 4
            for (int m = 0; m < NN; m++) {
                float av = __ldg(ar + m);
                float4 h = *(const float4*)(hs + m * 68 + d4);
                a0 = fmaf(av, h.x, a0); a1 = fmaf(av, h.y, a1);
                a2 = fmaf(av, h.z, a2); a3 = fmaf(av, h.w, a3);
            }
            xp[0] = a0; xp[1] = a1; xp[2] = a2; xp[3] = a3;
        }
    }
    __syncthreads();

    if (tid < DD) {
        float s = 0.f, ms = 0.f;
        for (int n = 0; n < NN; n++) {
            float m = atoms_mask[b * NN + n];
            s += xs[n * 68 + tid] * m;
            ms += m;
        }
        g_comp[b * DD + tid] = s / (ms + 1e-6f);
    }
}

// ===========================================================================
// Embed protein: g_bufA = emb_word[amino]
// ===========================================================================
__global__ void __launch_bounds__(256) embed_kernel(
    const int* __restrict__ amino, const float* __restrict__ emb)
{
    int idx = blockIdx.x * 256 + threadIdx.x;   // over B*L*16 float4s
    if (idx >= BB * LL * 16) return;
    int q = idx & 15, row = idx >> 4;
    ((float4*)g_bufA)[idx] = ((const float4*)emb)[amino[row] * 16 + q];
}

// ===========================================================================
// Conv 23x23 same + bias + relu, fp32 via packed f32x2.
// Tile 64 rows x 64 cols, 128 thr: thread = 8 rows x 4 cols.
// srcSel: 0 = A->B, 1 = B->A
// ===========================================================================
__global__ void __launch_bounds__(128, 3) conv_kernel(
    const float* __restrict__ ck, const float* __restrict__ cb,
    int layer, int srcSel)
{
    __shared__ float sh[86][88];
    __shared__ ull ksh[37][12];   // kernel row pairs, zero-padded index i+7

    const float* in = srcSel ? g_bufB : g_bufA;
    float* out      = srcSel ? g_bufA : g_bufB;

    const int b = blockIdx.y, h0 = blockIdx.x * 64, tid = threadIdx.x;

    const float* kk = ck + layer * 529;
    for (int idx = tid; idx < 37 * 12; idx += 128) {
        int i7 = idx / 12, jj = idx % 12, i = i7 - 7;
        float lo = 0.f, hi = 0.f;
        if (i >= 0 && i <= 22) {
            lo = kk[i * 23 + 2 * jj];
            if (2 * jj + 1 < 23) hi = kk[i * 23 + 2 * jj + 1];
        }
        ksh[i7][jj] = pk2(lo, hi);
    }
    for (int idx = tid; idx < 86 * 88; idx += 128) ((float*)sh)[idx] = 0.f;
    __syncthreads();

    const float* inb = in + (size_t)b * LL * DD;
    for (int idx = tid; idx < 86 * 16; idx += 128) {
        int s = idx >> 4, q = idx & 15;
        int gh = h0 + s - PADW;
        if (gh >= 0 && gh < LL) {
            float4 v = ((const float4*)(inb + (size_t)gh * DD))[q];
            float* p = &sh[s][PADW + 4 * q];
            p[0] = v.x; p[1] = v.y; p[2] = v.z; p[3] = v.w;
        }
    }
    __syncthreads();

    const int tx = tid & 15, ty = tid >> 4;
    const int w0 = tx * 4;

    ull acc[8][4];
    #pragma unroll
    for (int r = 0; r < 8; r++) acc[r][0] = acc[r][1] = acc[r][2] = acc[r][3] = 0ull;

    const float* base = &sh[ty * 8][w0];

    #pragma unroll 1
    for (int ir = 0; ir < 30; ir++) {
        ull pe[13], po[13];
        const float4* rp = (const float4*)(base + ir * 88);
        float4 v = rp[0];
        pe[0] = pk2(v.x, v.y); pe[1] = pk2(v.z, v.w); po[0] = pk2(v.y, v.z);
        float carry = v.w;
        #pragma unroll
        for (int q = 1; q <= 5; q++) {
            float4 u = rp[q];
            po[2*q-1] = pk2(carry, u.x);
            pe[2*q]   = pk2(u.x, u.y);
            pe[2*q+1] = pk2(u.z, u.w);
            po[2*q]   = pk2(u.y, u.z);
            carry = u.w;
        }
        { float4 u = rp[6];
          po[11] = pk2(carry, u.x);
          pe[12] = pk2(u.x, u.y);
          po[12] = pk2(u.y, u.z); }

        #pragma unroll
        for (int r = 0; r < 8; r++) {
            const ull* kp = ksh[ir - r + 7];   // zero rows when out of range
            #pragma unroll
            for (int jj = 0; jj < 12; jj++) {
                ull kv = kp[jj];
                FMA2(acc[r][0], pe[jj],   kv);
                FMA2(acc[r][1], po[jj],   kv);
                FMA2(acc[r][2], pe[jj+1], kv);
                FMA2(acc[r][3], po[jj+1], kv);
            }
        }
    }

    const float bias = cb[layer];
    float* outb = out + (size_t)b * LL * DD + (size_t)(h0 + ty * 8) * DD + w0;
    #pragma unroll
    for (int r = 0; r < 8; r++) {
        float4 v; float lo, hi;
        upk2(acc[r][0], lo, hi); v.x = fmaxf(lo + hi + bias, 0.f);
        upk2(acc[r][1], lo, hi); v.y = fmaxf(lo + hi + bias, 0.f);
        upk2(acc[r][2], lo, hi); v.z = fmaxf(lo + hi + bias, 0.f);
        upk2(acc[r][3], lo, hi); v.w = fmaxf(lo + hi + bias, 0.f);
        *(float4*)(outb + (size_t)r * DD) = v;
    }
}

// ===========================================================================
// Attention + protein pooling. 1 block / batch, 256 threads.
// dyn smem: Wt[64*68] + hsv[256*65] = 83968 B
// ===========================================================================
__global__ void __launch_bounds__(256) att_kernel(
    const float* __restrict__ amino_mask,
    const float* __restrict__ W_att, const float* __restrict__ b_att)
{
    extern __shared__ float sm[];
    float* Wt  = sm;                  // 64*68
    float* hsa = sm + 64 * 68;        // 256*65 per-thread hs scratch
    __shared__ float hv[64], sprot[64], sb[64], ssum;

    const int b = blockIdx.x, tid = threadIdx.x;
    const float* ps = g_bufB + (size_t)b * LL * DD;

    for (int o = tid; o < DD * DD; o += 256) {
        int e = o >> 6, d = o & 63;
        Wt[d * 68 + e] = W_att[o];
    }
    if (tid < 64) { sprot[tid] = 0.f; sb[tid] = b_att[tid]; }
    if (tid == 0) ssum = 0.f;
    __syncthreads();

    if (tid < 64) {
        float a = sb[tid];
        const float* wr = W_att + tid * 64;
        for (int d = 0; d < DD; d++) a = fmaf(g_comp[b * DD + d], wr[d], a);
        hv[tid] = fmaxf(a, 0.f);
    }
    __syncthreads();

    float prl[64];
    #pragma unroll
    for (int d = 0; d < 64; d++) prl[d] = 0.f;
    float msum = 0.f;
    float* myhs = hsa + tid * 65;

    for (int l = tid; l < LL; l += 256) {
        float m = amino_mask[b * LL + l];
        msum += m;
        const float4* xr = (const float4*)(ps + (size_t)l * DD);
        float4 x4[16];
        #pragma unroll
        for (int q = 0; q < 16; q++) x4[q] = xr[q];
        float wh = 0.f;
        #pragma unroll
        for (int e4 = 0; e4 < 64; e4 += 4) {
            float a0 = sb[e4], a1 = sb[e4+1], a2 = sb[e4+2], a3 = sb[e4+3];
            #pragma unroll
            for (int d = 0; d < DD; d++) {
                float x = ((const float*)x4)[d];
                float4 w = *(const float4*)(Wt + d * 68 + e4);
                a0 = fmaf(x, w.x, a0); a1 = fmaf(x, w.y, a1);
                a2 = fmaf(x, w.z, a2); a3 = fmaf(x, w.w, a3);
            }
            a0 = fmaxf(a0, 0.f) * m; a1 = fmaxf(a1, 0.f) * m;
            a2 = fmaxf(a2, 0.f) * m; a3 = fmaxf(a3, 0.f) * m;
            myhs[e4] = a0; myhs[e4+1] = a1; myhs[e4+2] = a2; myhs[e4+3] = a3;
            wh = fmaf(hv[e4], a0, wh);   wh = fmaf(hv[e4+1], a1, wh);
            wh = fmaf(hv[e4+2], a2, wh); wh = fmaf(hv[e4+3], a3, wh);
        }
        float w = tanhf(wh);
        #pragma unroll
        for (int d = 0; d < 64; d++) prl[d] = fmaf(w, myhs[d], prl[d]);
    }

    for (int off = 16; off; off >>= 1) msum += __shfl_xor_sync(~0u, msum, off);
    if ((tid & 31) == 0) atomicAdd(&ssum, msum);
    #pragma unroll
    for (int d = 0; d < 64; d++) {
        float v = prl[d];
        for (int off = 16; off; off >>= 1) v += __shfl_xor_sync(~0u, v, off);
        if ((tid & 31) == 0) atomicAdd(&sprot[d], v);
    }
    __syncthreads();
    if (tid < 64) g_prot[b * DD + tid] = sprot[tid] / (ssum + 1e-6f);
}

// ===========================================================================
// Output MLP: cat=[comp,prot]; 2x relu(cat@W^T+b); out = cat@W_int^T + b_int
// ===========================================================================
__global__ void __launch_bounds__(128) out_kernel(
    const float* __restrict__ W_out, const float* __restrict__ b_out,
    const float* __restrict__ W_int, const float* __restrict__ b_int,
    float* __restrict__ out)
{
    __shared__ float cat[128], nxt[128];
    const int b = blockIdx.x, t = threadIdx.x;
    if (t < 64) { cat[t] = g_comp[b * 64 + t]; cat[64 + t] = g_prot[b * 64 + t]; }
    __syncthreads();
    for (int j = 0; j < 2; j++) {
        float a = b_out[j * 128 + t];
        const float* wr = W_out + j * 16384 + t * 128;
        #pragma unroll 4
        for (int d = 0; d < 128; d++) a = fmaf(cat[d], wr[d], a);
        nxt[t] = fmaxf(a, 0.f);
        __syncthreads();
        cat[t] = nxt[t];
        __syncthreads();
    }
    if (t < 2) {
        float a = b_int[t];
        const float* wr = W_int + t * 128;
        for (int d = 0; d < 128; d++) a = fmaf(cat[d], wr[d], a);
        out[b * 2 + t] = a;
    }
}

// ===========================================================================
extern "C" void kernel_launch(void* const* d_in, const int* in_sizes, int n_in,
                              void* d_out, int out_size)
{
    const int*   atoms      = (const int*)  d_in[0];
    const float* atoms_mask = (const float*)d_in[1];
    const float* adjacency  = (const float*)d_in[2];
    const int*   amino      = (const int*)  d_in[3];
    const float* amino_mask = (const float*)d_in[4];
    const float* emb_fp     = (const float*)d_in[5];
    const float* emb_word   = (const float*)d_in[6];
    const float* W_gnn      = (const float*)d_in[7];
    const float* b_gnn      = (const float*)d_in[8];
    const float* conv_k     = (const float*)d_in[9];
    const float* conv_b     = (const float*)d_in[10];
    const float* W_att      = (const float*)d_in[11];
    const float* b_att      = (const float*)d_in[12];
    const float* W_out      = (const float*)d_in[13];
    const float* b_out      = (const float*)d_in[14];
    const float* W_int      = (const float*)d_in[15];
    const float* b_int      = (const float*)d_in[16];
    float* out = (float*)d_out;

    cudaFuncSetAttribute(gnn_kernel, cudaFuncAttributeMaxDynamicSharedMemorySize, 87296);
    cudaFuncSetAttribute(att_kernel, cudaFuncAttributeMaxDynamicSharedMemorySize, 83968);

    gnn_kernel<<<BB, 256, 87296>>>(atoms, atoms_mask, adjacency, emb_fp, W_gnn, b_gnn);

    embed_kernel<<<(BB * LL * 16 + 255) / 256, 256>>>(amino, emb_word);

    dim3 cgrid(LL / 64, BB);
    conv_kernel<<<cgrid, 128>>>(conv_k, conv_b, 0, 0);   // A -> B
    conv_kernel<<<cgrid, 128>>>(conv_k, conv_b, 1, 1);   // B -> A
    conv_kernel<<<cgrid, 128>>>(conv_k, conv_b, 2, 0);   // A -> B

    att_kernel<<<BB, 256, 83968>>>(amino_mask, W_att, b_att);

    out_kernel<<<BB, 128>>>(W_out, b_out, W_int, b_int, out);
}

// round 5
// speedup vs baseline: 3.1494x; 3.1476x over previous
#include <cuda_runtime.h>
#include <math.h>
#include <stdint.h>

typedef unsigned long long ull;
#define BB 256
#define NN 128
#define LL 2048
#define DD 64

__device__ float g_bufA[(size_t)BB * LL * DD];
__device__ float g_bufB[(size_t)BB * LL * DD];
__device__ float g_comp[BB * DD];
__device__ float g_prot[BB * DD];

// ---------------- helpers ----------------
__device__ __forceinline__ float tf32r(float x) {
    float r; asm("cvt.rna.tf32.f32 %0, %1;" : "=f"(r) : "f"(x)); return r;
}
__device__ __forceinline__ void mma_tf32(float* c, float a0, float a1, float a2, float a3,
                                         float b0, float b1) {
    asm volatile(
        "mma.sync.aligned.m16n8k8.row.col.f32.tf32.tf32.f32 "
        "{%0,%1,%2,%3}, {%4,%5,%6,%7}, {%8,%9}, {%0,%1,%2,%3};"
        : "+f"(c[0]), "+f"(c[1]), "+f"(c[2]), "+f"(c[3])
        : "r"(__float_as_uint(a0)), "r"(__float_as_uint(a1)),
          "r"(__float_as_uint(a2)), "r"(__float_as_uint(a3)),
          "r"(__float_as_uint(b0)), "r"(__float_as_uint(b1)));
}

// ---------------- conv: tf32 mma.sync Toeplitz ----------------
// tile = 128 rows x 64 cols; smem inS[150][92] + kS[529]
// inS[s][c] = in[h0 + s - 11][c - 12]  (zero outside)
// out[m,w] = sum_i sum_c inS[m+i][c] * B_i[c,w],  B_i[c,w] = k[i][c-w-1], c-w in [1,24)
#define CV_STRIDE 92
#define CV_SMEM   ((150 * CV_STRIDE + 544) * 4)

__global__ void __launch_bounds__(128) conv_mma(
    const float* __restrict__ ck, const float* __restrict__ cb,
    int layer, int srcSel)
{
    extern __shared__ float cvsm[];
    float* inS = cvsm;                      // 150 x 92
    float* kS  = cvsm + 150 * CV_STRIDE;    // 529 (tf32-converted)

    const float* in = srcSel ? g_bufB : g_bufA;
    float* out      = srcSel ? g_bufA : g_bufB;

    const int b  = blockIdx.y;
    const int h0 = blockIdx.x * 128;
    const int tid = threadIdx.x;

    // zero tile + stage tf32 kernel row-major
    float4 z4 = make_float4(0.f, 0.f, 0.f, 0.f);
    for (int idx = tid; idx < 150 * (CV_STRIDE / 4); idx += 128)
        ((float4*)inS)[idx] = z4;
    const float* kk = ck + layer * 529;
    for (int idx = tid; idx < 529; idx += 128) kS[idx] = tf32r(kk[idx]);
    __syncthreads();

    // fill real region (cols 12..75), tf32-converted
    const float* inb = in + (size_t)b * LL * DD;
    for (int idx = tid; idx < 150 * 16; idx += 128) {
        int s = idx >> 4, q = idx & 15;
        int gh = h0 + s - 11;
        if (gh >= 0 && gh < LL) {
            float4 v = ((const float4*)(inb + (size_t)gh * DD))[q];
            v.x = tf32r(v.x); v.y = tf32r(v.y); v.z = tf32r(v.z); v.w = tf32r(v.w);
            *(float4*)(inS + s * CV_STRIDE + 12 + 4 * q) = v;
        }
    }
    __syncthreads();

    const int lane = tid & 31, warp = tid >> 5;
    const int grp = lane >> 2, qd = lane & 3;   // t/4, t%4
    const int mbase = warp * 32;                // warp owns rows [mbase, mbase+32)

    float acc[2][8][4];
    #pragma unroll
    for (int rb = 0; rb < 2; rb++)
        #pragma unroll
        for (int n = 0; n < 8; n++)
            #pragma unroll
            for (int e = 0; e < 4; e++) acc[rb][n][e] = 0.f;

    #pragma unroll 1
    for (int i = 0; i < 23; i++) {
        // B fragments for the 4 K-steps: b[cc][ww] = kS[i][8k+cc-ww-1]
        const float* ks = kS + i * 23;
        float bf[4][2];
        #pragma unroll
        for (int k = 0; k < 4; k++) {
            int d0 = 8 * k + qd - grp;
            int d1 = d0 + 4;
            bf[k][0] = (d0 >= 1 && d0 < 24) ? ks[d0 - 1] : 0.f;
            bf[k][1] = (d1 >= 1 && d1 < 24) ? ks[d1 - 1] : 0.f;
        }
        const float* ar0 = inS + (mbase + grp + i) * CV_STRIDE + qd;
        #pragma unroll
        for (int rb = 0; rb < 2; rb++) {
            const float* ar = ar0 + rb * 16 * CV_STRIDE;
            #pragma unroll
            for (int p = 0; p < 11; p++) {
                float a0 = ar[8 * p];
                float a1 = ar[8 * p + 8 * CV_STRIDE];
                float a2 = ar[8 * p + 4];
                float a3 = ar[8 * p + 8 * CV_STRIDE + 4];
                #pragma unroll
                for (int k = 0; k < 4; k++) {
                    int n = p - k;
                    if (n >= 0 && n < 8)
                        mma_tf32(acc[rb][n], a0, a1, a2, a3, bf[k][0], bf[k][1]);
                }
            }
        }
    }

    // epilogue: bias + relu
    const float bias = cb[layer];
    float* ob = out + (size_t)b * LL * DD + (size_t)h0 * DD;
    #pragma unroll
    for (int rb = 0; rb < 2; rb++) {
        int m0 = mbase + rb * 16 + grp;
        #pragma unroll
        for (int n = 0; n < 8; n++) {
            int w = 8 * n + qd * 2;
            float2 v0, v1;
            v0.x = fmaxf(acc[rb][n][0] + bias, 0.f);
            v0.y = fmaxf(acc[rb][n][1] + bias, 0.f);
            v1.x = fmaxf(acc[rb][n][2] + bias, 0.f);
            v1.y = fmaxf(acc[rb][n][3] + bias, 0.f);
            *(float2*)(ob + (size_t)m0 * DD + w) = v0;
            *(float2*)(ob + (size_t)(m0 + 8) * DD + w) = v1;
        }
    }
}

// ===================== GNN (unchanged) =====================
__global__ void __launch_bounds__(256) gnn_kernel(
    const int* __restrict__ atoms, const float* __restrict__ atoms_mask,
    const float* __restrict__ adj, const float* __restrict__ emb_fp,
    const float* __restrict__ W_gnn, const float* __restrict__ b_gnn)
{
    extern __shared__ float smf[];
    float* xs = smf;
    float* hs = xs + 128 * 68;
    float* Wt = hs + 128 * 68;
    float* bv = Wt + 64 * 68;
    const int b = blockIdx.x, tid = threadIdx.x;

    for (int o = tid; o < NN * DD; o += 256) {
        int n = o >> 6, d = o & 63;
        xs[n * 68 + d] = emb_fp[atoms[b * NN + n] * DD + d];
    }
    for (int layer = 0; layer < 3; layer++) {
        __syncthreads();
        for (int o = tid; o < DD * DD; o += 256) {
            int e = o >> 6, d = o & 63;
            Wt[d * 68 + e] = W_gnn[layer * DD * DD + o];
        }
        if (tid < DD) bv[tid] = b_gnn[layer * DD + tid];
        __syncthreads();
        for (int g = tid; g < NN * 16; g += 256) {
            int n = g >> 4, e4 = (g & 15) * 4;
            float a0 = bv[e4], a1 = bv[e4+1], a2 = bv[e4+2], a3 = bv[e4+3];
            const float* xr = xs + n * 68;
            #pragma unroll 4
            for (int d = 0; d < DD; d++) {
                float x = xr[d];
                float4 w = *(const float4*)(Wt + d * 68 + e4);
                a0 = fmaf(x, w.x, a0); a1 = fmaf(x, w.y, a1);
                a2 = fmaf(x, w.z, a2); a3 = fmaf(x, w.w, a3);
            }
            float* hr = hs + n * 68 + e4;
            hr[0] = fmaxf(a0, 0.f); hr[1] = fmaxf(a1, 0.f);
            hr[2] = fmaxf(a2, 0.f); hr[3] = fmaxf(a3, 0.f);
        }
        __syncthreads();
        const float* adjb = adj + (size_t)b * NN * NN;
        for (int g = tid; g < NN * 16; g += 256) {
            int n = g >> 4, d4 = (g & 15) * 4;
            float* xp = xs + n * 68 + d4;
            float a0 = xp[0], a1 = xp[1], a2 = xp[2], a3 = xp[3];
            const float* ar = adjb + n * NN;
            #pragma unroll 4
            for (int m = 0; m < NN; m++) {
                float av = __ldg(ar + m);
                float4 h = *(const float4*)(hs + m * 68 + d4);
                a0 = fmaf(av, h.x, a0); a1 = fmaf(av, h.y, a1);
                a2 = fmaf(av, h.z, a2); a3 = fmaf(av, h.w, a3);
            }
            xp[0] = a0; xp[1] = a1; xp[2] = a2; xp[3] = a3;
        }
    }
    __syncthreads();
    if (tid < DD) {
        float s = 0.f, ms = 0.f;
        for (int n = 0; n < NN; n++) {
            float m = atoms_mask[b * NN + n];
            s += xs[n * 68 + tid] * m;
            ms += m;
        }
        g_comp[b * DD + tid] = s / (ms + 1e-6f);
    }
}

__global__ void __launch_bounds__(256) embed_kernel(
    const int* __restrict__ amino, const float* __restrict__ emb)
{
    int idx = blockIdx.x * 256 + threadIdx.x;
    if (idx >= BB * LL * 16) return;
    int q = idx & 15, row = idx >> 4;
    ((float4*)g_bufA)[idx] = ((const float4*)emb)[amino[row] * 16 + q];
}

// ===================== attention (unchanged) =====================
__global__ void __launch_bounds__(256) att_kernel(
    const float* __restrict__ amino_mask,
    const float* __restrict__ W_att, const float* __restrict__ b_att)
{
    extern __shared__ float smf[];
    float* Wt  = smf;
    float* hsa = smf + 64 * 68;
    __shared__ float hv[64], sprot[64], sb[64], ssum;
    const int b = blockIdx.x, tid = threadIdx.x;
    const float* ps = g_bufB + (size_t)b * LL * DD;

    for (int o = tid; o < DD * DD; o += 256) {
        int e = o >> 6, d = o & 63;
        Wt[d * 68 + e] = W_att[o];
    }
    if (tid < 64) { sprot[tid] = 0.f; sb[tid] = b_att[tid]; }
    if (tid == 0) ssum = 0.f;
    __syncthreads();
    if (tid < 64) {
        float a = sb[tid];
        const float* wr = W_att + tid * 64;
        for (int d = 0; d < DD; d++) a = fmaf(g_comp[b * DD + d], wr[d], a);
        hv[tid] = fmaxf(a, 0.f);
    }
    __syncthreads();

    float prl[64];
    #pragma unroll
    for (int d = 0; d < 64; d++) prl[d] = 0.f;
    float msum = 0.f;
    float* myhs = hsa + tid * 65;

    for (int l = tid; l < LL; l += 256) {
        float m = amino_mask[b * LL + l];
        msum += m;
        const float4* xr = (const float4*)(ps + (size_t)l * DD);
        float4 x4[16];
        #pragma unroll
        for (int q = 0; q < 16; q++) x4[q] = xr[q];
        float wh = 0.f;
        #pragma unroll
        for (int e4 = 0; e4 < 64; e4 += 4) {
            float a0 = sb[e4], a1 = sb[e4+1], a2 = sb[e4+2], a3 = sb[e4+3];
            #pragma unroll
            for (int d = 0; d < DD; d++) {
                float x = ((const float*)x4)[d];
                float4 w = *(const float4*)(Wt + d * 68 + e4);
                a0 = fmaf(x, w.x, a0); a1 = fmaf(x, w.y, a1);
                a2 = fmaf(x, w.z, a2); a3 = fmaf(x, w.w, a3);
            }
            a0 = fmaxf(a0, 0.f) * m; a1 = fmaxf(a1, 0.f) * m;
            a2 = fmaxf(a2, 0.f) * m; a3 = fmaxf(a3, 0.f) * m;
            myhs[e4] = a0; myhs[e4+1] = a1; myhs[e4+2] = a2; myhs[e4+3] = a3;
            wh = fmaf(hv[e4], a0, wh);   wh = fmaf(hv[e4+1], a1, wh);
            wh = fmaf(hv[e4+2], a2, wh); wh = fmaf(hv[e4+3], a3, wh);
        }
        float w = tanhf(wh);
        #pragma unroll
        for (int d = 0; d < 64; d++) prl[d] = fmaf(w, myhs[d], prl[d]);
    }
    for (int off = 16; off; off >>= 1) msum += __shfl_xor_sync(~0u, msum, off);
    if ((tid & 31) == 0) atomicAdd(&ssum, msum);
    #pragma unroll
    for (int d = 0; d < 64; d++) {
        float v = prl[d];
        for (int off = 16; off; off >>= 1) v += __shfl_xor_sync(~0u, v, off);
        if ((tid & 31) == 0) atomicAdd(&sprot[d], v);
    }
    __syncthreads();
    if (tid < 64) g_prot[b * DD + tid] = sprot[tid] / (ssum + 1e-6f);
}

__global__ void __launch_bounds__(128) out_kernel(
    const float* __restrict__ W_out, const float* __restrict__ b_out,
    const float* __restrict__ W_int, const float* __restrict__ b_int,
    float* __restrict__ out)
{
    __shared__ float cat[128], nxt[128];
    const int b = blockIdx.x, t = threadIdx.x;
    if (t < 64) { cat[t] = g_comp[b * 64 + t]; cat[64 + t] = g_prot[b * 64 + t]; }
    __syncthreads();
    for (int j = 0; j < 2; j++) {
        float a = b_out[j * 128 + t];
        const float* wr = W_out + j * 16384 + t * 128;
        #pragma unroll 4
        for (int d = 0; d < 128; d++) a = fmaf(cat[d], wr[d], a);
        nxt[t] = fmaxf(a, 0.f);
        __syncthreads();
        cat[t] = nxt[t];
        __syncthreads();
    }
    if (t < 2) {
        float a = b_int[t];
        const float* wr = W_int + t * 128;
        for (int d = 0; d < 128; d++) a = fmaf(cat[d], wr[d], a);
        out[b * 2 + t] = a;
    }
}

// ===========================================================================
extern "C" void kernel_launch(void* const* d_in, const int* in_sizes, int n_in,
                              void* d_out, int out_size)
{
    const int*   atoms      = (const int*)  d_in[0];
    const float* atoms_mask = (const float*)d_in[1];
    const float* adjacency  = (const float*)d_in[2];
    const int*   amino      = (const int*)  d_in[3];
    const float* amino_mask = (const float*)d_in[4];
    const float* emb_fp     = (const float*)d_in[5];
    const float* emb_word   = (const float*)d_in[6];
    const float* W_gnn      = (const float*)d_in[7];
    const float* b_gnn      = (const float*)d_in[8];
    const float* conv_k     = (const float*)d_in[9];
    const float* conv_b     = (const float*)d_in[10];
    const float* W_att      = (const float*)d_in[11];
    const float* b_att      = (const float*)d_in[12];
    const float* W_out      = (const float*)d_in[13];
    const float* b_out      = (const float*)d_in[14];
    const float* W_int      = (const float*)d_in[15];
    const float* b_int      = (const float*)d_in[16];
    float* out = (float*)d_out;

    cudaFuncSetAttribute(gnn_kernel, cudaFuncAttributeMaxDynamicSharedMemorySize, 87296);
    cudaFuncSetAttribute(att_kernel, cudaFuncAttributeMaxDynamicSharedMemorySize, 83968);
    cudaFuncSetAttribute(conv_mma,   cudaFuncAttributeMaxDynamicSharedMemorySize, CV_SMEM);

    gnn_kernel<<<BB, 256, 87296>>>(atoms, atoms_mask, adjacency, emb_fp, W_gnn, b_gnn);
    embed_kernel<<<(BB * LL * 16 + 255) / 256, 256>>>(amino, emb_word);

    dim3 cgrid(LL / 128, BB);
    conv_mma<<<cgrid, 128, CV_SMEM>>>(conv_k, conv_b, 0, 0);   // A -> B
    conv_mma<<<cgrid, 128, CV_SMEM>>>(conv_k, conv_b, 1, 1);   // B -> A
    conv_mma<<<cgrid, 128, CV_SMEM>>>(conv_k, conv_b, 2, 0);   // A -> B

    att_kernel<<<BB, 256, 83968>>>(amino_mask, W_att, b_att);
    out_kernel<<<BB, 128>>>(W_out, b_out, W_int, b_int, out);
}

// round 6
// speedup vs baseline: 3.6018x; 1.1436x over previous
#include <cuda_runtime.h>
#include <math.h>
#include <stdint.h>

#define BB 256
#define NN 128
#define LL 2048
#define DD 64

__device__ float g_bufA[(size_t)BB * LL * DD];
__device__ float g_bufB[(size_t)BB * LL * DD];
__device__ float g_comp[BB * DD];
__device__ float g_prot[BB * DD];

// ---------------- helpers ----------------
__device__ __forceinline__ float tf32r(float x) {
    float r; asm("cvt.rna.tf32.f32 %0, %1;" : "=f"(r) : "f"(x)); return r;
}
__device__ __forceinline__ void mma_tf32(float* c, float a0, float a1, float a2, float a3,
                                         float b0, float b1) {
    asm volatile(
        "mma.sync.aligned.m16n8k8.row.col.f32.tf32.tf32.f32 "
        "{%0,%1,%2,%3}, {%4,%5,%6,%7}, {%8,%9}, {%0,%1,%2,%3};"
        : "+f"(c[0]), "+f"(c[1]), "+f"(c[2]), "+f"(c[3])
        : "r"(__float_as_uint(a0)), "r"(__float_as_uint(a1)),
          "r"(__float_as_uint(a2)), "r"(__float_as_uint(a3)),
          "r"(__float_as_uint(b0)), "r"(__float_as_uint(b1)));
}

// ---------------- conv: tf32 mma Toeplitz, 64-row tiles ----------------
// inS[s][c] = in[h0 + s - 11][c - 12]; out[m,w] = sum_{i,c} inS[m+i][c]*k[i][c-w-1]
#define CV_STRIDE 92
#define CV_ROWS   86
#define CV_SMEM   ((CV_ROWS * CV_STRIDE + 532) * 4)

__global__ void __launch_bounds__(128) conv_mma(
    const float* __restrict__ ck, const float* __restrict__ cb,
    int layer, int srcSel, int gather,
    const int* __restrict__ amino, const float* __restrict__ emb)
{
    extern __shared__ float cvsm[];
    float* inS = cvsm;                        // 86 x 92
    float* kS  = cvsm + CV_ROWS * CV_STRIDE;  // 529

    const float* in = srcSel ? g_bufB : g_bufA;
    float* out      = srcSel ? g_bufA : g_bufB;

    const int b  = blockIdx.y;
    const int h0 = blockIdx.x * 64;
    const int tid = threadIdx.x;

    float4 z4 = make_float4(0.f, 0.f, 0.f, 0.f);
    for (int idx = tid; idx < CV_ROWS * (CV_STRIDE / 4); idx += 128)
        ((float4*)inS)[idx] = z4;
    const float* kk = ck + layer * 529;
    for (int idx = tid; idx < 529; idx += 128) kS[idx] = tf32r(kk[idx]);
    __syncthreads();

    const float* inb = in + (size_t)b * LL * DD;
    const int* am = amino + b * LL;
    for (int idx = tid; idx < CV_ROWS * 16; idx += 128) {
        int s = idx >> 4, q = idx & 15;
        int gh = h0 + s - 11;
        if (gh >= 0 && gh < LL) {
            float4 v;
            if (gather) v = ((const float4*)(emb + (size_t)am[gh] * DD))[q];
            else        v = ((const float4*)(inb + (size_t)gh * DD))[q];
            v.x = tf32r(v.x); v.y = tf32r(v.y); v.z = tf32r(v.z); v.w = tf32r(v.w);
            *(float4*)(inS + s * CV_STRIDE + 12 + 4 * q) = v;
        }
    }
    __syncthreads();

    const int lane = tid & 31, warp = tid >> 5;
    const int grp = lane >> 2, qd = lane & 3;
    const int mbase = warp * 16;

    float acc[8][4];
    #pragma unroll
    for (int n = 0; n < 8; n++)
        #pragma unroll
        for (int e = 0; e < 4; e++) acc[n][e] = 0.f;

    #pragma unroll 1
    for (int i = 0; i < 23; i++) {
        const float* ks = kS + i * 23;
        float bf[4][2];
        #pragma unroll
        for (int k = 0; k < 4; k++) {
            int d0 = 8 * k + qd - grp;
            int d1 = d0 + 4;
            bf[k][0] = (d0 >= 1 && d0 < 24) ? ks[d0 - 1] : 0.f;
            bf[k][1] = (d1 >= 1 && d1 < 24) ? ks[d1 - 1] : 0.f;
        }
        const float* ar = inS + (mbase + grp + i) * CV_STRIDE + qd;
        #pragma unroll
        for (int p = 0; p < 11; p++) {
            float a0 = ar[8 * p];
            float a1 = ar[8 * p + 8 * CV_STRIDE];
            float a2 = ar[8 * p + 4];
            float a3 = ar[8 * p + 8 * CV_STRIDE + 4];
            #pragma unroll
            for (int k = 0; k < 4; k++) {
                int n = p - k;
                if (n >= 0 && n < 8)
                    mma_tf32(acc[n], a0, a1, a2, a3, bf[k][0], bf[k][1]);
            }
        }
    }

    const float bias = cb[layer];
    float* ob = out + (size_t)b * LL * DD + (size_t)h0 * DD;
    int m0 = mbase + grp;
    #pragma unroll
    for (int n = 0; n < 8; n++) {
        int w = 8 * n + qd * 2;
        float2 v0, v1;
        v0.x = fmaxf(acc[n][0] + bias, 0.f);
        v0.y = fmaxf(acc[n][1] + bias, 0.f);
        v1.x = fmaxf(acc[n][2] + bias, 0.f);
        v1.y = fmaxf(acc[n][3] + bias, 0.f);
        *(float2*)(ob + (size_t)m0 * DD + w) = v0;
        *(float2*)(ob + (size_t)(m0 + 8) * DD + w) = v1;
    }
}

// ---------------- hs GEMM: hs = relu(ps @ W_att^T + b_att) * mask ----------------
// tile 128 l-rows x 64 e-cols, K=64. ps from g_bufB, hs -> g_bufA.
#define HS_SMEM ((128 * 68 + 64 * 68 + 64) * 4)

__global__ void __launch_bounds__(128) hs_gemm(
    const float* __restrict__ W_att, const float* __restrict__ b_att,
    const float* __restrict__ amino_mask)
{
    extern __shared__ float hsm[];
    float* psS = hsm;                 // 128 x 68
    float* wS  = hsm + 128 * 68;      // 64 x 68 (row e)
    float* bS  = wS + 64 * 68;        // 64

    const int b  = blockIdx.y;
    const int l0 = blockIdx.x * 128;
    const int tid = threadIdx.x;
    const float* ps = g_bufB + (size_t)b * LL * DD;

    for (int idx = tid; idx < 128 * 16; idx += 128) {
        int s = idx >> 4, q = idx & 15;
        float4 v = ((const float4*)(ps + (size_t)(l0 + s) * DD))[q];
        v.x = tf32r(v.x); v.y = tf32r(v.y); v.z = tf32r(v.z); v.w = tf32r(v.w);
        *(float4*)(psS + s * 68 + 4 * q) = v;
    }
    for (int idx = tid; idx < 64 * 16; idx += 128) {
        int e = idx >> 4, q = idx & 15;
        float4 v = ((const float4*)(W_att + e * 64))[q];
        v.x = tf32r(v.x); v.y = tf32r(v.y); v.z = tf32r(v.z); v.w = tf32r(v.w);
        *(float4*)(wS + e * 68 + 4 * q) = v;
    }
    if (tid < 64) bS[tid] = b_att[tid];
    __syncthreads();

    const int lane = tid & 31, warp = tid >> 5;
    const int grp = lane >> 2, qd = lane & 3;
    const int mbase = warp * 32;

    float acc[2][8][4];
    #pragma unroll
    for (int rb = 0; rb < 2; rb++)
        #pragma unroll
        for (int n = 0; n < 8; n++)
            #pragma unroll
            for (int e = 0; e < 4; e++) acc[rb][n][e] = 0.f;

    #pragma unroll 1
    for (int ks = 0; ks < 8; ks++) {
        float bf[8][2];
        #pragma unroll
        for (int n = 0; n < 8; n++) {
            const float* wr = wS + (8 * n + grp) * 68 + 8 * ks + qd;
            bf[n][0] = wr[0];
            bf[n][1] = wr[4];
        }
        #pragma unroll
        for (int rb = 0; rb < 2; rb++) {
            const float* ar = psS + (mbase + rb * 16 + grp) * 68 + 8 * ks + qd;
            float a0 = ar[0], a1 = ar[8 * 68], a2 = ar[4], a3 = ar[8 * 68 + 4];
            #pragma unroll
            for (int n = 0; n < 8; n++)
                mma_tf32(acc[rb][n], a0, a1, a2, a3, bf[n][0], bf[n][1]);
        }
    }

    float* hb = g_bufA + (size_t)b * LL * DD;
    const float* mk = amino_mask + b * LL;
    #pragma unroll
    for (int rb = 0; rb < 2; rb++) {
        int l = l0 + mbase + rb * 16 + grp;
        float m0v = mk[l], m1v = mk[l + 8];
        #pragma unroll
        for (int n = 0; n < 8; n++) {
            int e = 8 * n + 2 * qd;
            float2 v0, v1;
            v0.x = fmaxf(acc[rb][n][0] + bS[e], 0.f) * m0v;
            v0.y = fmaxf(acc[rb][n][1] + bS[e + 1], 0.f) * m0v;
            v1.x = fmaxf(acc[rb][n][2] + bS[e], 0.f) * m1v;
            v1.y = fmaxf(acc[rb][n][3] + bS[e + 1], 0.f) * m1v;
            *(float2*)(hb + (size_t)l * DD + e) = v0;
            *(float2*)(hb + (size_t)(l + 8) * DD + e) = v1;
        }
    }
}

// ---------------- attention finalize: tanh-weighted pooling ----------------
__global__ void __launch_bounds__(256) att_fin(
    const float* __restrict__ amino_mask,
    const float* __restrict__ W_att, const float* __restrict__ b_att)
{
    __shared__ float hv[64], sprot[64], ssum;
    const int b = blockIdx.x, tid = threadIdx.x;

    if (tid < 64) {
        float a = b_att[tid];
        const float* wr = W_att + tid * 64;
        #pragma unroll 4
        for (int d = 0; d < DD; d++) a = fmaf(g_comp[b * DD + d], wr[d], a);
        hv[tid] = fmaxf(a, 0.f);
        sprot[tid] = 0.f;
    }
    if (tid == 0) ssum = 0.f;
    __syncthreads();

    const float* hsb = g_bufA + (size_t)b * LL * DD;
    float prl[64];
    #pragma unroll
    for (int d = 0; d < 64; d++) prl[d] = 0.f;
    float msum = 0.f;

    for (int l = tid; l < LL; l += 256) {
        msum += amino_mask[b * LL + l];
        const float4* xr = (const float4*)(hsb + (size_t)l * DD);
        float4 x4[16];
        #pragma unroll
        for (int q = 0; q < 16; q++) x4[q] = xr[q];
        float wh = 0.f;
        #pragma unroll
        for (int d = 0; d < 64; d++) wh = fmaf(hv[d], ((const float*)x4)[d], wh);
        float w = tanhf(wh);
        #pragma unroll
        for (int d = 0; d < 64; d++) prl[d] = fmaf(w, ((const float*)x4)[d], prl[d]);
    }

    for (int off = 16; off; off >>= 1) msum += __shfl_xor_sync(~0u, msum, off);
    if ((tid & 31) == 0) atomicAdd(&ssum, msum);
    #pragma unroll
    for (int d = 0; d < 64; d++) {
        float v = prl[d];
        for (int off = 16; off; off >>= 1) v += __shfl_xor_sync(~0u, v, off);
        if ((tid & 31) == 0) atomicAdd(&sprot[d], v);
    }
    __syncthreads();
    if (tid < 64) g_prot[b * DD + tid] = sprot[tid] / (ssum + 1e-6f);
}

// ===================== GNN (unchanged) =====================
__global__ void __launch_bounds__(256) gnn_kernel(
    const int* __restrict__ atoms, const float* __restrict__ atoms_mask,
    const float* __restrict__ adj, const float* __restrict__ emb_fp,
    const float* __restrict__ W_gnn, const float* __restrict__ b_gnn)
{
    extern __shared__ float smf[];
    float* xs = smf;
    float* hs = xs + 128 * 68;
    float* Wt = hs + 128 * 68;
    float* bv = Wt + 64 * 68;
    const int b = blockIdx.x, tid = threadIdx.x;

    for (int o = tid; o < NN * DD; o += 256) {
        int n = o >> 6, d = o & 63;
        xs[n * 68 + d] = emb_fp[atoms[b * NN + n] * DD + d];
    }
    for (int layer = 0; layer < 3; layer++) {
        __syncthreads();
        for (int o = tid; o < DD * DD; o += 256) {
            int e = o >> 6, d = o & 63;
            Wt[d * 68 + e] = W_gnn[layer * DD * DD + o];
        }
        if (tid < DD) bv[tid] = b_gnn[layer * DD + tid];
        __syncthreads();
        for (int g = tid; g < NN * 16; g += 256) {
            int n = g >> 4, e4 = (g & 15) * 4;
            float a0 = bv[e4], a1 = bv[e4+1], a2 = bv[e4+2], a3 = bv[e4+3];
            const float* xr = xs + n * 68;
            #pragma unroll 4
            for (int d = 0; d < DD; d++) {
                float x = xr[d];
                float4 w = *(const float4*)(Wt + d * 68 + e4);
                a0 = fmaf(x, w.x, a0); a1 = fmaf(x, w.y, a1);
                a2 = fmaf(x, w.z, a2); a3 = fmaf(x, w.w, a3);
            }
            float* hr = hs + n * 68 + e4;
            hr[0] = fmaxf(a0, 0.f); hr[1] = fmaxf(a1, 0.f);
            hr[2] = fmaxf(a2, 0.f); hr[3] = fmaxf(a3, 0.f);
        }
        __syncthreads();
        const float* adjb = adj + (size_t)b * NN * NN;
        for (int g = tid; g < NN * 16; g += 256) {
            int n = g >> 4, d4 = (g & 15) * 4;
            float* xp = xs + n * 68 + d4;
            float a0 = xp[0], a1 = xp[1], a2 = xp[2], a3 = xp[3];
            const float* ar = adjb + n * NN;
            #pragma unroll 4
            for (int m = 0; m < NN; m++) {
                float av = __ldg(ar + m);
                float4 h = *(const float4*)(hs + m * 68 + d4);
                a0 = fmaf(av, h.x, a0); a1 = fmaf(av, h.y, a1);
                a2 = fmaf(av, h.z, a2); a3 = fmaf(av, h.w, a3);
            }
            xp[0] = a0; xp[1] = a1; xp[2] = a2; xp[3] = a3;
        }
    }
    __syncthreads();
    if (tid < DD) {
        float s = 0.f, ms = 0.f;
        for (int n = 0; n < NN; n++) {
            float m = atoms_mask[b * NN + n];
            s += xs[n * 68 + tid] * m;
            ms += m;
        }
        g_comp[b * DD + tid] = s / (ms + 1e-6f);
    }
}

// ===================== output MLP (unchanged) =====================
__global__ void __launch_bounds__(128) out_kernel(
    const float* __restrict__ W_out, const float* __restrict__ b_out,
    const float* __restrict__ W_int, const float* __restrict__ b_int,
    float* __restrict__ out)
{
    __shared__ float cat[128], nxt[128];
    const int b = blockIdx.x, t = threadIdx.x;
    if (t < 64) { cat[t] = g_comp[b * 64 + t]; cat[64 + t] = g_prot[b * 64 + t]; }
    __syncthreads();
    for (int j = 0; j < 2; j++) {
        float a = b_out[j * 128 + t];
        const float* wr = W_out + j * 16384 + t * 128;
        #pragma unroll 4
        for (int d = 0; d < 128; d++) a = fmaf(cat[d], wr[d], a);
        nxt[t] = fmaxf(a, 0.f);
        __syncthreads();
        cat[t] = nxt[t];
        __syncthreads();
    }
    if (t < 2) {
        float a = b_int[t];
        const float* wr = W_int + t * 128;
        for (int d = 0; d < 128; d++) a = fmaf(cat[d], wr[d], a);
        out[b * 2 + t] = a;
    }
}

// ===========================================================================
extern "C" void kernel_launch(void* const* d_in, const int* in_sizes, int n_in,
                              void* d_out, int out_size)
{
    const int*   atoms      = (const int*)  d_in[0];
    const float* atoms_mask = (const float*)d_in[1];
    const float* adjacency  = (const float*)d_in[2];
    const int*   amino      = (const int*)  d_in[3];
    const float* amino_mask = (const float*)d_in[4];
    const float* emb_fp     = (const float*)d_in[5];
    const float* emb_word   = (const float*)d_in[6];
    const float* W_gnn      = (const float*)d_in[7];
    const float* b_gnn      = (const float*)d_in[8];
    const float* conv_k     = (const float*)d_in[9];
    const float* conv_b     = (const float*)d_in[10];
    const float* W_att      = (const float*)d_in[11];
    const float* b_att      = (const float*)d_in[12];
    const float* W_out      = (const float*)d_in[13];
    const float* b_out      = (const float*)d_in[14];
    const float* W_int      = (const float*)d_in[15];
    const float* b_int      = (const float*)d_in[16];
    float* out = (float*)d_out;

    cudaFuncSetAttribute(gnn_kernel, cudaFuncAttributeMaxDynamicSharedMemorySize, 87296);
    cudaFuncSetAttribute(conv_mma,   cudaFuncAttributeMaxDynamicSharedMemorySize, CV_SMEM);
    cudaFuncSetAttribute(hs_gemm,    cudaFuncAttributeMaxDynamicSharedMemorySize, HS_SMEM);

    gnn_kernel<<<BB, 256, 87296>>>(atoms, atoms_mask, adjacency, emb_fp, W_gnn, b_gnn);

    dim3 cgrid(LL / 64, BB);
    conv_mma<<<cgrid, 128, CV_SMEM>>>(conv_k, conv_b, 0, 0, 1, amino, emb_word); // gather -> B
    conv_mma<<<cgrid, 128, CV_SMEM>>>(conv_k, conv_b, 1, 1, 0, amino, emb_word); // B -> A
    conv_mma<<<cgrid, 128, CV_SMEM>>>(conv_k, conv_b, 2, 0, 0, amino, emb_word); // A -> B

    dim3 hgrid(LL / 128, BB);
    hs_gemm<<<hgrid, 128, HS_SMEM>>>(W_att, b_att, amino_mask);

    att_fin<<<BB, 256>>>(amino_mask, W_att, b_att);
    out_kernel<<<BB, 128>>>(W_out, b_out, W_int, b_int, out);
}